// round 15
// baseline (speedup 1.0000x reference)
#include <cuda_runtime.h>
#include <cstdint>

#define NT 9               // Taylor terms n = 0..8
#define SCALE 0.35355339059327373f

__constant__ float c_invfact[NT] = {
    1.0f, 1.0f, 0.5f, 1.0f/6.0f, 1.0f/24.0f, 1.0f/120.0f, 1.0f/720.0f,
    1.0f/5040.0f, 1.0f/40320.0f
};

__device__ __forceinline__ float rcpf(float x) {
    float r; asm("rcp.approx.ftz.f32 %0, %1;" : "=f"(r) : "f"(x)); return r;
}
__device__ __forceinline__ uint32_t smem_u32(const void* p) {
    return (uint32_t)__cvta_generic_to_shared(p);
}
__device__ __forceinline__ float dsmem_ld(uint32_t laddr, uint32_t rank) {
    uint32_t ra; float v;
    asm("mapa.shared::cluster.u32 %0, %1, %2;" : "=r"(ra) : "r"(laddr), "r"(rank));
    asm volatile("ld.shared::cluster.f32 %0, [%1];" : "=f"(v) : "r"(ra));
    return v;
}
#define CLUSTER_ARRIVE() asm volatile("barrier.cluster.arrive.aligned;" ::: "memory")
#define CLUSTER_WAIT()   asm volatile("barrier.cluster.wait.aligned;" ::: "memory")
#define CLUSTER_SYNC() do { CLUSTER_ARRIVE(); CLUSTER_WAIT(); } while (0)

// 32 CTAs x 256 threads, clusters of 8 (one cluster per 2048-row).
// CTA handles elements [256*blk, 256*blk+256) = 2 heads; produces table cols 2r, 2r+1.
__global__ __launch_bounds__(256) __cluster_dims__(8, 1, 1)
void fused_all(const float* __restrict__ q, const float* __restrict__ k,
               const float* __restrict__ v,
               const float* __restrict__ wq, const float* __restrict__ wk,
               const float* __restrict__ wv, const float* __restrict__ wf,
               const float* __restrict__ lnw, const float* __restrict__ lnb,
               float* __restrict__ out) {
    __shared__ __align__(16) float s_G[16][12];   // (sum_sm g^n)/n!      [sn][n]
    __shared__ __align__(16) float s_H[16][12];   // (sum_sm g^n gvf)/n!  [sn][n]
    __shared__ __align__(16) float s_c[2][16][12];
    __shared__ float s_Q[2][12];
    __shared__ float s_red[8][9];
    __shared__ float s_C[2][12];
    __shared__ float s_colg[2][16], s_colv[2][16];
    __shared__ float s_l1[8], s_l2[8];
    __shared__ float s_lnp[2];

    const int t = threadIdx.x;
    const int lane = t & 31, warp = t >> 5;
    const int blk = blockIdx.x, rank = blk & 7;
    const int base = blk * 256;
    const int li = rank * 256 + t;        // index within the 2048 row

    // prefetch ALL gmem inputs up-front (MLP overlap hides the LN-tail latency)
    const float qv = q[base + t];
    const float kv = k[base + t];
    const float vv = v[base + t];
    const float wl = lnw[li];
    const float bl = lnb[li];

    // ── produce table columns col = 2*rank + (t>=128): 8 threads per dot, float4 loads ──
    {
        const int grp = t >> 7;
        const int col = rank * 2 + grp;
        const int u = t & 127, sm = u >> 3, dp = u & 7;
        const float4* Aq = (const float4*)(wq + sm * 128 + dp * 16);
        const float4* Bk = (const float4*)(wk + col * 128 + dp * 16);
        const float4* Av = (const float4*)(wv + col * 128 + dp * 16);
        const float4* Bf = (const float4*)(wf + sm * 128 + dp * 16);
        float sg = 0.f, sv = 0.f;
        #pragma unroll
        for (int j = 0; j < 4; j++) {
            float4 a = Aq[j], b = Bk[j];
            sg = fmaf(a.x, b.x, sg); sg = fmaf(a.y, b.y, sg);
            sg = fmaf(a.z, b.z, sg); sg = fmaf(a.w, b.w, sg);
            float4 c2 = Av[j], d2 = Bf[j];
            sv = fmaf(c2.x, d2.x, sv); sv = fmaf(c2.y, d2.y, sv);
            sv = fmaf(c2.z, d2.z, sv); sv = fmaf(c2.w, d2.w, sv);
        }
        #pragma unroll
        for (int o = 4; o; o >>= 1) {
            sg += __shfl_xor_sync(0xffffffffu, sg, o);
            sv += __shfl_xor_sync(0xffffffffu, sv, o);
        }
        if (dp == 0) { s_colg[grp][sm] = sg * SCALE; s_colv[grp][sm] = sv; }
    }
    __syncthreads();

    // ── table power sums, parallel across 8 warps: warp w -> term n = w+1 ──
    // lane = (ci, sm); one 16-lane dual reduction per warp. n=0: G=16 const,
    // H0 = sum gv rides as a 3rd value in warp 0 only. Same trees -> deterministic.
    {
        const int ci = lane >> 4, sm = lane & 15;
        const float x  = s_colg[ci][sm];
        const float gv = s_colv[ci][sm];
        const int n = warp + 1;                       // 1..8
        // p = x^n, branchless binary exponentiation
        const float x2 = x * x;
        const float x4 = x2 * x2;
        const float x8 = x4 * x4;
        float p = (n & 1) ? x : 1.f;
        p *= (n & 2) ? x2 : 1.f;
        p *= (n & 4) ? x4 : 1.f;
        p *= (n & 8) ? x8 : 1.f;
        float Gs = p, Hs = p * gv, Hs0 = gv;
        #pragma unroll
        for (int o = 8; o; o >>= 1) {
            Gs  += __shfl_xor_sync(0xffffffffu, Gs,  o);
            Hs  += __shfl_xor_sync(0xffffffffu, Hs,  o);
            Hs0 += __shfl_xor_sync(0xffffffffu, Hs0, o);
        }
        if (sm == 0) {
            const int col = rank * 2 + ci;
            s_G[col][n] = Gs * c_invfact[n];
            s_H[col][n] = Hs * c_invfact[n];
            if (warp == 0) { s_G[col][0] = 16.f; s_H[col][0] = Hs0; }
        }
    }
    // each thread's table writes precede its own cluster-arrive -> peer-visible after wait
    CLUSTER_ARRIVE();

    // ── Qn per head (hidden under cluster skew): qv^1..qv^8 ──
    {
        float pv[8];
        pv[0] = qv;
        #pragma unroll
        for (int i = 1; i < 8; i++) pv[i] = pv[i - 1] * qv;
        #pragma unroll
        for (int o = 16; o >= 8; o >>= 1) {
            #pragma unroll
            for (int i = 0; i < 8; i++) pv[i] += __shfl_xor_sync(0xffffffffu, pv[i], o);
        }
        #pragma unroll
        for (int r = 0; r < 4; r++) {
            float lo = pv[r], hi = pv[r + 4];
            float keep = (lane & 4) ? hi : lo, send = (lane & 4) ? lo : hi;
            pv[r] = keep + __shfl_xor_sync(0xffffffffu, send, 4);
        }
        #pragma unroll
        for (int r = 0; r < 2; r++) {
            float lo = pv[r], hi = pv[r + 2];
            float keep = (lane & 2) ? hi : lo, send = (lane & 2) ? lo : hi;
            pv[r] = keep + __shfl_xor_sync(0xffffffffu, send, 2);
        }
        {
            float lo = pv[0], hi = pv[1];
            float keep = (lane & 1) ? hi : lo, send = (lane & 1) ? lo : hi;
            pv[0] = keep + __shfl_xor_sync(0xffffffffu, send, 1);
        }
        if (lane < 8) s_red[warp][lane] = pv[0];     // sum_warp qv^{lane+1}
    }
    __syncthreads();
    if (t < 16) {
        int h = t >> 3, n = t & 7;
        s_Q[h][n + 1] = (s_red[4 * h][n] + s_red[4 * h + 1][n])
                      + (s_red[4 * h + 2][n] + s_red[4 * h + 3][n]);
    }
    if (t < 2) s_Q[t][0] = 128.f;
    // s_Q visibility covered by the post-gather __syncthreads below.

    // ── cluster exchange: gather the other 14 columns via DSMEM ──
    CLUSTER_WAIT();
    for (int idx = t; idx < 288; idx += 256) {       // 2 arrays x 16 cols x 9 terms
        int a = idx / 144, rem = idx - a * 144;
        int col = rem / 9, n = rem - col * 9;
        int rk = col >> 1;
        if (rk != rank) {
            float* dst = a ? &s_H[col][n] : &s_G[col][n];
            *dst = dsmem_ld(smem_u32(dst), (uint32_t)rk);
        }
    }
    __syncthreads();

    // per-head Horner coefficients c[h][sn][n] = Q[h][n] * Gn[sn][n]
    for (int idx = t; idx < 288; idx += 256) {
        int h2 = idx / 144, rem = idx - h2 * 144;
        int sn = rem / 9, n = rem - sn * 9;
        s_c[h2][sn][n] = s_Q[h2][n] * s_G[sn][n];
    }
    __syncthreads();

    // ── core: per rn, Z[sn] Horner in kv -> 1/Z; accumulate T[n] ──
    const int h = t >> 7;
    const float* cb = &s_c[h][0][0];
    float T[9];
    #pragma unroll
    for (int n = 0; n < 9; n++) T[n] = 0.f;

    #pragma unroll 4
    for (int sn = 0; sn < 16; sn++) {
        float4 a0 = *(const float4*)(cb + sn * 12);
        float4 a1 = *(const float4*)(cb + sn * 12 + 4);
        float  a8 = cb[sn * 12 + 8];
        float z = a8;
        z = fmaf(z, kv, a1.w);
        z = fmaf(z, kv, a1.z);
        z = fmaf(z, kv, a1.y);
        z = fmaf(z, kv, a1.x);
        z = fmaf(z, kv, a0.w);
        z = fmaf(z, kv, a0.z);
        z = fmaf(z, kv, a0.y);
        z = fmaf(z, kv, a0.x);
        float W = rcpf(z);
        float4 h0 = *(const float4*)(&s_H[sn][0]);
        float4 h1 = *(const float4*)(&s_H[sn][4]);
        float  h8 = s_H[sn][8];
        T[0] = fmaf(h0.x, W, T[0]);
        T[1] = fmaf(h0.y, W, T[1]);
        T[2] = fmaf(h0.z, W, T[2]);
        T[3] = fmaf(h0.w, W, T[3]);
        T[4] = fmaf(h1.x, W, T[4]);
        T[5] = fmaf(h1.y, W, T[5]);
        T[6] = fmaf(h1.z, W, T[6]);
        T[7] = fmaf(h1.w, W, T[7]);
        T[8] = fmaf(h8,   W, T[8]);
    }
    {
        float kp = vv;
        #pragma unroll
        for (int n = 0; n < 9; n++) { T[n] *= kp; kp *= kv; }
    }

    // warp-reduce 16 (padded) values: halving over bits 4..1 + final bit-0 stage
    {
        float rv[16];
        #pragma unroll
        for (int i = 0; i < 9; i++) rv[i] = T[i];
        #pragma unroll
        for (int i = 9; i < 16; i++) rv[i] = 0.f;
        #pragma unroll
        for (int r = 0; r < 8; r++) {
            float lo = rv[r], hi = rv[r + 8];
            float keep = (lane & 16) ? hi : lo, send = (lane & 16) ? lo : hi;
            rv[r] = keep + __shfl_xor_sync(0xffffffffu, send, 16);
        }
        #pragma unroll
        for (int r = 0; r < 4; r++) {
            float lo = rv[r], hi = rv[r + 4];
            float keep = (lane & 8) ? hi : lo, send = (lane & 8) ? lo : hi;
            rv[r] = keep + __shfl_xor_sync(0xffffffffu, send, 8);
        }
        #pragma unroll
        for (int r = 0; r < 2; r++) {
            float lo = rv[r], hi = rv[r + 2];
            float keep = (lane & 4) ? hi : lo, send = (lane & 4) ? lo : hi;
            rv[r] = keep + __shfl_xor_sync(0xffffffffu, send, 4);
        }
        {
            float lo = rv[0], hi = rv[1];
            float keep = (lane & 2) ? hi : lo, send = (lane & 2) ? lo : hi;
            rv[0] = keep + __shfl_xor_sync(0xffffffffu, send, 2);
        }
        rv[0] += __shfl_xor_sync(0xffffffffu, rv[0], 1);
        int j = lane >> 1;
        if (((lane & 1) == 0) && j < 9) s_red[warp][j] = rv[0];
    }
    __syncthreads();
    if (t < 18) {
        int hh = t / 9, n = t - hh * 9;
        s_C[hh][n] = (s_red[4 * hh][n] + s_red[4 * hh + 1][n])
                   + (s_red[4 * hh + 2][n] + s_red[4 * hh + 3][n]);
    }
    __syncthreads();

    // out[rm] = sum_n qv^n * C[n] (Horner), + residual
    float r = s_C[h][8];
    #pragma unroll
    for (int n = 7; n >= 0; n--) r = fmaf(r, qv, s_C[h][n]);
    const float x = qv + r;

    // ── LayerNorm across the 2048-row via cluster DSMEM ──
    float s1 = x, s2 = x * x;
    #pragma unroll
    for (int o = 16; o; o >>= 1) {
        s1 += __shfl_xor_sync(0xffffffffu, s1, o);
        s2 += __shfl_xor_sync(0xffffffffu, s2, o);
    }
    if (lane == 0) { s_l1[warp] = s1; s_l2[warp] = s2; }
    __syncthreads();
    if (t == 0) {
        float ts = 0.f, ts2 = 0.f;
        #pragma unroll
        for (int w = 0; w < 8; w++) { ts += s_l1[w]; ts2 += s_l2[w]; }
        s_lnp[0] = ts;
        s_lnp[1] = ts2;
    }
    // t0's s_lnp store precedes t0's arrive; peers read after wait.
    CLUSTER_SYNC();                       // partials visible cluster-wide
    if (t < 8) {                          // parallel remote gather
        s_l1[t] = dsmem_ld(smem_u32(&s_lnp[0]), (uint32_t)t);
        s_l2[t] = dsmem_ld(smem_u32(&s_lnp[1]), (uint32_t)t);
    }
    __syncthreads();

    // all threads compute mu/rstd from the 8 partials (broadcast LDS, fixed order)
    float S = 0.f, S2 = 0.f;
    #pragma unroll
    for (int j = 0; j < 8; j++) { S += s_l1[j]; S2 += s_l2[j]; }
    const float mu   = S * (1.f / 2048.f);
    const float var  = S2 * (1.f / 2048.f) - mu * mu;
    const float rstd = rsqrtf(var + 1e-5f);

    out[base + t] = (x - mu) * rstd * wl + bl;

    CLUSTER_SYNC();                       // keep smem alive for peers' DSMEM reads
}

extern "C" void kernel_launch(void* const* d_in, const int* in_sizes, int n_in,
                              void* d_out, int out_size) {
    const float* query = (const float*)d_in[0];
    const float* key   = (const float*)d_in[1];
    const float* value = (const float*)d_in[2];
    const float* wq    = (const float*)d_in[3];
    const float* wk    = (const float*)d_in[4];
    const float* wv    = (const float*)d_in[5];
    const float* wf    = (const float*)d_in[6];
    const float* lnw   = (const float*)d_in[7];
    const float* lnb   = (const float*)d_in[8];
    float* out = (float*)d_out;

    fused_all<<<32, 256>>>(query, key, value, wq, wk, wv, wf, lnw, lnb, out);
}